// round 10
// baseline (speedup 1.0000x reference)
#include <cuda_runtime.h>
#include <cuda_bf16.h>

#define T_STEPS 4096
#define BATCH   256
#define HID     32
#define G3      96

// Scratch. g_xg layout: [t][gate][j]; gates 0,1 (r,z) pre-scaled by 0.5 with
// both biases folded; gate 2 (n) carries b_ih only. Padded 2 steps.
__device__ float g_xg[(T_STEPS + 2) * G3];
__device__ float g_hs[T_STEPS * HID];

__device__ __forceinline__ float tanh_a(float x) {
    float y;
    asm("tanh.approx.f32 %0, %1;" : "=f"(y) : "f"(x));
    return y;
}

// ---------------------------------------------------------------------------
// Kernel 1: xg precompute for batch row 255.
// g <  64 (r,z): 0.5 * (b_ih + b_hh + W x)   [pre-scaled for tanh-sigmoid]
// g >= 64 (n) :        (b_ih        + W x)   [b_hh_n stays inside hn]
// ---------------------------------------------------------------------------
__global__ void precompute_xg(const float* __restrict__ x,
                              const float* __restrict__ w_ih,
                              const float* __restrict__ b_ih,
                              const float* __restrict__ b_hh) {
    int idx = blockIdx.x * blockDim.x + threadIdx.x;
    if (idx >= T_STEPS * G3) return;
    int t = idx / G3;
    int g = idx - t * G3;
    float x0 = __ldg(&x[t * (BATCH * 2) + (BATCH - 1) * 2 + 0]);
    float x1 = __ldg(&x[t * (BATCH * 2) + (BATCH - 1) * 2 + 1]);
    float v = b_ih[g] + w_ih[g * 2 + 0] * x0 + w_ih[g * 2 + 1] * x1;
    if (g < 2 * HID) v = 0.5f * (v + b_hh[g]);
    g_xg[t * G3 + g] = v;
}

// ---------------------------------------------------------------------------
// Kernel 2: sequential GRU, 6 warps, k-split as in R9 — but h is exchanged
// via __shfl_sync from registers (every warp redundantly computes h[j] in
// lane j, so the values are warp-local). No smem round-trip for h: removes
// the STS-commit -> LDS serialization from the critical path.
// Warp wid = (gate g = wid>>1, k-half = wid&1). Partial dots staged
// (double-buffered), ONE __syncthreads, redundant finish.
// ---------------------------------------------------------------------------
__global__ void __launch_bounds__(192, 1)
gru_seq(const float* __restrict__ w_hh, const float* __restrict__ b_hh) {
    __shared__ float sh_p [2][6][HID];               // partial dots [buf][wid][j]
    __shared__ float sh_xn[2][HID];

    const int wid  = threadIdx.x >> 5;   // 0..5
    const int g    = wid >> 1;           // gate: 0=r 1=z 2=n
    const int half = wid & 1;            // k-half
    const int j    = threadIdx.x & 31;   // hidden unit / row
    const int kb   = half * 16;          // k-base for this warp

    // 16 scalar weights: row g*32+j, k in [kb, kb+16). r,z pre-scaled 0.5.
    float wk[16];
#pragma unroll
    for (int p = 0; p < 16; p++) wk[p] = w_hh[(g * HID + j) * HID + kb + p];
    if (g < 2) {
#pragma unroll
        for (int p = 0; p < 16; p++) wk[p] *= 0.5f;
    }
    const float bn = b_hh[2 * HID + j];

    float h_old = 0.0f;                  // lane j holds h[j] (all warps)

    // xg streams: w0 -> xr column, w2 -> xz column, w5 -> xn column.
    const bool has_x = (wid == 0) || (wid == 2) || (wid == 5);
    const int  col   = (wid == 0) ? 0 : (wid == 2) ? 1 : 2;
    const float* xs  = g_xg + col * HID + j;
    float xc = 0.0f, x1 = 0.0f;
    if (has_x) { xc = xs[0 * G3]; x1 = xs[1 * G3]; }
    __syncthreads();

#pragma unroll 2
    for (int t = 0; t < T_STEPS; t++) {
        const int p = t & 1;
        float x2 = 0.0f;
        if (has_x) x2 = xs[(t + 2) * G3];          // prefetch t+2

        // ---- Phase A: partial dot over this warp's k-half via shfl ----
        float init = (wid == 0 || wid == 2) ? xc : (wid == 4 ? bn : 0.0f);
        float a0 = init, a1 = 0.0f, a2 = 0.0f, a3 = 0.0f;
#pragma unroll
        for (int k = 0; k < 4; k++) {
            float h0 = __shfl_sync(0xFFFFFFFFu, h_old, kb + 4 * k + 0);
            float h1 = __shfl_sync(0xFFFFFFFFu, h_old, kb + 4 * k + 1);
            float h2 = __shfl_sync(0xFFFFFFFFu, h_old, kb + 4 * k + 2);
            float h3 = __shfl_sync(0xFFFFFFFFu, h_old, kb + 4 * k + 3);
            a0 = fmaf(wk[4 * k + 0], h0, a0);
            a1 = fmaf(wk[4 * k + 1], h1, a1);
            a2 = fmaf(wk[4 * k + 2], h2, a2);
            a3 = fmaf(wk[4 * k + 3], h3, a3);
        }
        sh_p[p][wid][j] = (a0 + a1) + (a2 + a3);
        if (wid == 5) sh_xn[p][j] = xc;
        __syncthreads();                           // the ONE block barrier

        // ---- Phase B: every warp redundantly finishes h ----
        float r0 = sh_p[p][0][j], r1 = sh_p[p][1][j];
        float z0 = sh_p[p][2][j], z1 = sh_p[p][3][j];
        float n0 = sh_p[p][4][j], n1 = sh_p[p][5][j];
        float xn = sh_xn[p][j];
        float rp = r0 + r1;                        // 0.5-scaled presum
        float zp = z0 + z1;
        float hn = n0 + n1;                        // Wn.h + bn
        float r  = fmaf(tanh_a(rp), 0.5f, 0.5f);
        float z  = fmaf(tanh_a(zp), 0.5f, 0.5f);
        float u  = z * h_old;                      // under MUFU shadow
        float v  = 1.0f - z;
        float n  = tanh_a(fmaf(r, hn, xn));
        float h  = fmaf(n, v, u);                  // (1-z)*n + z*h_old
        h_old = h;                                 // h stays in registers
        if (wid == 1) g_hs[t * HID + j] = h;       // x-idle warp does the STG

        xc = x1; x1 = x2;
    }
}

// ---------------------------------------------------------------------------
// Kernel 3: out[t] = b_fc + w_fc . h_t  (warp per timestep)
// ---------------------------------------------------------------------------
__global__ void fc_kernel(const float* __restrict__ w_fc,
                          const float* __restrict__ b_fc,
                          float* __restrict__ out) {
    int t = blockIdx.x;
    int j = threadIdx.x;
    float v = w_fc[j] * g_hs[t * HID + j];
#pragma unroll
    for (int off = 16; off > 0; off >>= 1)
        v += __shfl_xor_sync(0xFFFFFFFFu, v, off);
    if (j == 0) out[t] = v + b_fc[0];
}

// ---------------------------------------------------------------------------
extern "C" void kernel_launch(void* const* d_in, const int* in_sizes, int n_in,
                              void* d_out, int out_size) {
    const float* x    = (const float*)d_in[0];
    const float* w_ih = (const float*)d_in[1];
    const float* w_hh = (const float*)d_in[2];
    const float* b_ih = (const float*)d_in[3];
    const float* b_hh = (const float*)d_in[4];
    const float* w_fc = (const float*)d_in[5];
    const float* b_fc = (const float*)d_in[6];
    float* out = (float*)d_out;

    precompute_xg<<<(T_STEPS * G3 + 255) / 256, 256>>>(x, w_ih, b_ih, b_hh);
    gru_seq<<<1, 192>>>(w_hh, b_hh);
    fc_kernel<<<T_STEPS, HID>>>(w_fc, b_fc, out);
}

// round 11
// speedup vs baseline: 1.1324x; 1.1324x over previous
#include <cuda_runtime.h>
#include <cuda_bf16.h>

#define T_STEPS 4096
#define BATCH   256
#define HID     32
#define G3      96

// Scratch. g_xg layout: [t][gate][j]; gates 0,1 (r,z) pre-scaled by 0.5 with
// both biases folded; gate 2 (n) carries b_ih only. Padded 2 steps.
__device__ float g_xg[(T_STEPS + 2) * G3];
__device__ float g_hs[T_STEPS * HID];

// ---------------------------------------------------------------------------
// f32x2 helpers (sm_100+)
// ---------------------------------------------------------------------------
__device__ __forceinline__ unsigned long long ffma2(unsigned long long a,
                                                    unsigned long long b,
                                                    unsigned long long c) {
    unsigned long long d;
    asm("fma.rn.f32x2 %0, %1, %2, %3;" : "=l"(d) : "l"(a), "l"(b), "l"(c));
    return d;
}
__device__ __forceinline__ unsigned long long mul2(unsigned long long a,
                                                   unsigned long long b) {
    unsigned long long d;
    asm("mul.rn.f32x2 %0, %1, %2;" : "=l"(d) : "l"(a), "l"(b));
    return d;
}
__device__ __forceinline__ unsigned long long pack2(float lo, float hi) {
    unsigned long long d;
    asm("mov.b64 %0, {%1, %2};"
        : "=l"(d) : "r"(__float_as_uint(lo)), "r"(__float_as_uint(hi)));
    return d;
}
__device__ __forceinline__ float f32x2_sum2(unsigned long long a,
                                            unsigned long long b) {
    unsigned int al, ah, bl, bh;
    asm("mov.b64 {%0, %1}, %2;" : "=r"(al), "=r"(ah) : "l"(a));
    asm("mov.b64 {%0, %1}, %2;" : "=r"(bl), "=r"(bh) : "l"(b));
    return (__uint_as_float(al) + __uint_as_float(ah)) +
           (__uint_as_float(bl) + __uint_as_float(bh));
}
__device__ __forceinline__ float tanh_a(float x) {
    float y;
    asm("tanh.approx.f32 %0, %1;" : "=f"(y) : "f"(x));
    return y;
}

// ---------------------------------------------------------------------------
// Kernel 1: xg precompute for batch row 255.
// g <  64 (r,z): 0.5 * (b_ih + b_hh + W x)   [pre-scaled for tanh-sigmoid]
// g >= 64 (n) :        (b_ih        + W x)   [b_hh_n stays inside hn]
// ---------------------------------------------------------------------------
__global__ void precompute_xg(const float* __restrict__ x,
                              const float* __restrict__ w_ih,
                              const float* __restrict__ b_ih,
                              const float* __restrict__ b_hh) {
    int idx = blockIdx.x * blockDim.x + threadIdx.x;
    if (idx >= T_STEPS * G3) return;
    int t = idx / G3;
    int g = idx - t * G3;
    float x0 = __ldg(&x[t * (BATCH * 2) + (BATCH - 1) * 2 + 0]);
    float x1 = __ldg(&x[t * (BATCH * 2) + (BATCH - 1) * 2 + 1]);
    float v = b_ih[g] + w_ih[g * 2 + 0] * x0 + w_ih[g * 2 + 1] * x1;
    if (g < 2 * HID) v = 0.5f * (v + b_hh[g]);
    g_xg[t * G3 + g] = v;
}

// ---------------------------------------------------------------------------
// Kernel 2: sequential GRU, 6 warps (R9 structure). Warp wid = (gate g =
// wid>>1, k-half = wid&1): 8 FFMA2 per warp on its k-half. SINGLE CHANGE vs
// R9: gate partials staged in float4-packed per-j slots so Phase B reads
// them with 2 conflict-free LDS.128 instead of 7 scalar LDS.
//   sh_a[buf][j] = (r0, r1, z0, z1)   <- warps 0..3 write lane wid
//   sh_b[buf][j] = (n0, n1, xn, -)    <- warp 4 lane 0, warp 5 lanes 1,2
// ---------------------------------------------------------------------------
__global__ void __launch_bounds__(192, 1)
gru_seq(const float* __restrict__ w_hh, const float* __restrict__ b_hh) {
    __shared__ __align__(16) float h_priv[6][HID];   // per-warp h copy
    __shared__ __align__(16) float sh_a[2][HID][4];  // (r0,r1,z0,z1) per j
    __shared__ __align__(16) float sh_b[2][HID][4];  // (n0,n1,xn,-)  per j

    const int wid  = threadIdx.x >> 5;   // 0..5
    const int g    = wid >> 1;           // gate: 0=r 1=z 2=n
    const int half = wid & 1;            // k-half
    const int j    = threadIdx.x & 31;   // hidden unit / row

    // 8 packed weight pairs: row g*32+j, k in [half*16, half*16+16).
    unsigned long long wk[8];
    const unsigned long long* W = (const unsigned long long*)w_hh;
#pragma unroll
    for (int p = 0; p < 8; p++) wk[p] = W[(g * HID + j) * 16 + half * 8 + p];
    if (g < 2) {
        const unsigned long long h2 = pack2(0.5f, 0.5f);
#pragma unroll
        for (int p = 0; p < 8; p++) wk[p] = mul2(wk[p], h2);
    }
    const float bn = b_hh[2 * HID + j];

    h_priv[wid][j] = 0.0f;
    float h_old = 0.0f;

    // xg streams: w0 -> xr column, w2 -> xz column, w5 -> xn column.
    const bool has_x = (wid == 0) || (wid == 2) || (wid == 5);
    const int  col   = (wid == 0) ? 0 : (wid == 2) ? 1 : 2;
    const float* xs  = g_xg + col * HID + j;
    float xc = 0.0f, x1 = 0.0f;
    if (has_x) { xc = xs[0 * G3]; x1 = xs[1 * G3]; }
    __syncthreads();

#pragma unroll 2
    for (int t = 0; t < T_STEPS; t++) {
        const int p = t & 1;
        float x2 = 0.0f;
        if (has_x) x2 = xs[(t + 2) * G3];          // prefetch t+2

        // ---- Phase A: partial dot over this warp's k-half ----
        float init = (wid == 0 || wid == 2) ? xc : (wid == 4 ? bn : 0.0f);
        unsigned long long a0 = pack2(init, 0.0f);
        unsigned long long a1 = pack2(0.0f, 0.0f);
        const ulonglong2* hp =
            (const ulonglong2*)(h_priv[wid] + half * 16);
#pragma unroll
        for (int i = 0; i < 4; i++) {
            ulonglong2 hq = hp[i];
            a0 = ffma2(wk[2 * i + 0], hq.x, a0);
            a1 = ffma2(wk[2 * i + 1], hq.y, a1);
        }
        float part = f32x2_sum2(a0, a1);
        if (wid < 4) sh_a[p][j][wid] = part;       // (r0,r1,z0,z1)
        else         sh_b[p][j][wid - 4] = part;   // (n0,n1)
        if (wid == 5) sh_b[p][j][2] = xc;          // xn
        __syncthreads();                           // the ONE block barrier

        // ---- Phase B: every warp redundantly finishes h (2 LDS.128) ----
        float4 A = *(const float4*)sh_a[p][j];     // r0,r1,z0,z1
        float4 B = *(const float4*)sh_b[p][j];     // n0,n1,xn,-
        float rp = A.x + A.y;                      // 0.5-scaled presum
        float zp = A.z + A.w;
        float hn = B.x + B.y;                      // Wn.h + bn
        float r  = fmaf(tanh_a(rp), 0.5f, 0.5f);
        float z  = fmaf(tanh_a(zp), 0.5f, 0.5f);
        float u  = z * h_old;                      // under MUFU shadow
        float v  = 1.0f - z;
        float n  = tanh_a(fmaf(r, hn, B.z));
        float h  = fmaf(n, v, u);                  // (1-z)*n + z*h_old
        h_old = h;
        h_priv[wid][j] = h;                        // private copy
        if (wid == 1) g_hs[t * HID + j] = h;       // x-idle warp does the STG
        asm volatile("" ::: "memory");             // order STS before next LDS

        xc = x1; x1 = x2;
    }
}

// ---------------------------------------------------------------------------
// Kernel 3: out[t] = b_fc + w_fc . h_t  (warp per timestep)
// ---------------------------------------------------------------------------
__global__ void fc_kernel(const float* __restrict__ w_fc,
                          const float* __restrict__ b_fc,
                          float* __restrict__ out) {
    int t = blockIdx.x;
    int j = threadIdx.x;
    float v = w_fc[j] * g_hs[t * HID + j];
#pragma unroll
    for (int off = 16; off > 0; off >>= 1)
        v += __shfl_xor_sync(0xFFFFFFFFu, v, off);
    if (j == 0) out[t] = v + b_fc[0];
}

// ---------------------------------------------------------------------------
extern "C" void kernel_launch(void* const* d_in, const int* in_sizes, int n_in,
                              void* d_out, int out_size) {
    const float* x    = (const float*)d_in[0];
    const float* w_ih = (const float*)d_in[1];
    const float* w_hh = (const float*)d_in[2];
    const float* b_ih = (const float*)d_in[3];
    const float* b_hh = (const float*)d_in[4];
    const float* w_fc = (const float*)d_in[5];
    const float* b_fc = (const float*)d_in[6];
    float* out = (float*)d_out;

    precompute_xg<<<(T_STEPS * G3 + 255) / 256, 256>>>(x, w_ih, b_ih, b_hh);
    gru_seq<<<1, 192>>>(w_hh, b_hh);
    fc_kernel<<<T_STEPS, HID>>>(w_fc, b_fc, out);
}

// round 12
// speedup vs baseline: 1.1872x; 1.0484x over previous
#include <cuda_runtime.h>
#include <cuda_bf16.h>

#define T_STEPS 4096
#define BATCH   256
#define HID     32
#define G3      96

// Scratch. g_xg layout: [t][gate][j]; gates 0,1 (r,z) pre-scaled by 0.5 with
// both biases folded; gate 2 (n) carries b_ih only. Padded 2 steps.
__device__ float g_xg[(T_STEPS + 2) * G3];
__device__ float g_hs[T_STEPS * HID];

// ---------------------------------------------------------------------------
// f32x2 helpers (sm_100+)
// ---------------------------------------------------------------------------
__device__ __forceinline__ unsigned long long ffma2(unsigned long long a,
                                                    unsigned long long b,
                                                    unsigned long long c) {
    unsigned long long d;
    asm("fma.rn.f32x2 %0, %1, %2, %3;" : "=l"(d) : "l"(a), "l"(b), "l"(c));
    return d;
}
__device__ __forceinline__ unsigned long long mul2(unsigned long long a,
                                                   unsigned long long b) {
    unsigned long long d;
    asm("mul.rn.f32x2 %0, %1, %2;" : "=l"(d) : "l"(a), "l"(b));
    return d;
}
__device__ __forceinline__ unsigned long long pack2(float lo, float hi) {
    unsigned long long d;
    asm("mov.b64 %0, {%1, %2};"
        : "=l"(d) : "r"(__float_as_uint(lo)), "r"(__float_as_uint(hi)));
    return d;
}
__device__ __forceinline__ float f32x2_sum2(unsigned long long a,
                                            unsigned long long b) {
    unsigned int al, ah, bl, bh;
    asm("mov.b64 {%0, %1}, %2;" : "=r"(al), "=r"(ah) : "l"(a));
    asm("mov.b64 {%0, %1}, %2;" : "=r"(bl), "=r"(bh) : "l"(b));
    return (__uint_as_float(al) + __uint_as_float(ah)) +
           (__uint_as_float(bl) + __uint_as_float(bh));
}
__device__ __forceinline__ float tanh_a(float x) {
    float y;
    asm("tanh.approx.f32 %0, %1;" : "=f"(y) : "f"(x));
    return y;
}

// ---------------------------------------------------------------------------
// Kernel 1: xg precompute for batch row 255.
// g <  64 (r,z): 0.5 * (b_ih + b_hh + W x)   [pre-scaled for tanh-sigmoid]
// g >= 64 (n) :        (b_ih        + W x)   [b_hh_n stays inside hn]
// ---------------------------------------------------------------------------
__global__ void precompute_xg(const float* __restrict__ x,
                              const float* __restrict__ w_ih,
                              const float* __restrict__ b_ih,
                              const float* __restrict__ b_hh) {
    int idx = blockIdx.x * blockDim.x + threadIdx.x;
    if (idx >= T_STEPS * G3) return;
    int t = idx / G3;
    int g = idx - t * G3;
    float x0 = __ldg(&x[t * (BATCH * 2) + (BATCH - 1) * 2 + 0]);
    float x1 = __ldg(&x[t * (BATCH * 2) + (BATCH - 1) * 2 + 1]);
    float v = b_ih[g] + w_ih[g * 2 + 0] * x0 + w_ih[g * 2 + 1] * x1;
    if (g < 2 * HID) v = 0.5f * (v + b_hh[g]);
    g_xg[t * G3 + g] = v;
}

// ---------------------------------------------------------------------------
// Kernel 2: sequential GRU, 6 warps. Warp wid = (gate g = wid>>1, k-half =
// wid&1): each warp computes a 16-wide k-half of its gate's dot (8 FFMA2).
// Raw partial sums staged (double-buffered); ONE __syncthreads; then every
// warp redundantly finishes (sum halves -> activations -> h), keeping a
// warp-private h copy. r,z weights/xg pre-scaled by 0.5.
// Role balance: w0 init xr, w2 init xz, w4 init bn, w5 stages xn, w1 does
// the g_hs store.
// ---------------------------------------------------------------------------
__global__ void __launch_bounds__(192, 1)
gru_seq(const float* __restrict__ w_hh, const float* __restrict__ b_hh) {
    __shared__ __align__(16) float h_priv[6][HID];   // per-warp h copy
    __shared__ float sh_p [2][6][HID];               // partial dots [buf][wid][j]
    __shared__ float sh_xn[2][HID];

    const int wid  = threadIdx.x >> 5;   // 0..5
    const int g    = wid >> 1;           // gate: 0=r 1=z 2=n
    const int half = wid & 1;            // k-half
    const int j    = threadIdx.x & 31;   // hidden unit / row

    // 8 packed weight pairs: row g*32+j, k in [half*16, half*16+16).
    unsigned long long wk[8];
    const unsigned long long* W = (const unsigned long long*)w_hh;
#pragma unroll
    for (int p = 0; p < 8; p++) wk[p] = W[(g * HID + j) * 16 + half * 8 + p];
    if (g < 2) {
        const unsigned long long h2 = pack2(0.5f, 0.5f);
#pragma unroll
        for (int p = 0; p < 8; p++) wk[p] = mul2(wk[p], h2);
    }
    const float bn = b_hh[2 * HID + j];

    h_priv[wid][j] = 0.0f;
    float h_old = 0.0f;

    // xg streams: w0 -> xr column, w2 -> xz column, w5 -> xn column.
    const bool has_x = (wid == 0) || (wid == 2) || (wid == 5);
    const int  col   = (wid == 0) ? 0 : (wid == 2) ? 1 : 2;
    const float* xs  = g_xg + col * HID + j;
    float xc = 0.0f, x1 = 0.0f;
    if (has_x) { xc = xs[0 * G3]; x1 = xs[1 * G3]; }
    __syncthreads();

#pragma unroll 2
    for (int t = 0; t < T_STEPS; t++) {
        const int p = t & 1;
        float x2 = 0.0f;
        if (has_x) x2 = xs[(t + 2) * G3];          // prefetch t+2

        // ---- Phase A: partial dot over this warp's k-half ----
        float init = (wid == 0 || wid == 2) ? xc : (wid == 4 ? bn : 0.0f);
        unsigned long long a0 = pack2(init, 0.0f);
        unsigned long long a1 = pack2(0.0f, 0.0f);
        const ulonglong2* hp =
            (const ulonglong2*)(h_priv[wid] + half * 16);
#pragma unroll
        for (int i = 0; i < 4; i++) {
            ulonglong2 hq = hp[i];
            a0 = ffma2(wk[2 * i + 0], hq.x, a0);
            a1 = ffma2(wk[2 * i + 1], hq.y, a1);
        }
        sh_p[p][wid][j] = f32x2_sum2(a0, a1);
        if (wid == 5) sh_xn[p][j] = xc;
        __syncthreads();                           // the ONE block barrier

        // ---- Phase B: every warp redundantly finishes h ----
        float r0 = sh_p[p][0][j], r1 = sh_p[p][1][j];
        float z0 = sh_p[p][2][j], z1 = sh_p[p][3][j];
        float n0 = sh_p[p][4][j], n1 = sh_p[p][5][j];
        float xn = sh_xn[p][j];
        float rp = r0 + r1;                        // 0.5-scaled presum
        float zp = z0 + z1;
        float hn = n0 + n1;                        // Wn.h + bn
        float r  = fmaf(tanh_a(rp), 0.5f, 0.5f);
        float z  = fmaf(tanh_a(zp), 0.5f, 0.5f);
        float u  = z * h_old;                      // under MUFU shadow
        float v  = 1.0f - z;
        float n  = tanh_a(fmaf(r, hn, xn));
        float h  = fmaf(n, v, u);                  // (1-z)*n + z*h_old
        h_old = h;
        h_priv[wid][j] = h;                        // private copy
        if (wid == 1) g_hs[t * HID + j] = h;       // x-idle warp does the STG
        asm volatile("" ::: "memory");             // order STS before next LDS

        xc = x1; x1 = x2;
    }
}

// ---------------------------------------------------------------------------
// Kernel 3: out[t] = b_fc + w_fc . h_t  (warp per timestep)
// ---------------------------------------------------------------------------
__global__ void fc_kernel(const float* __restrict__ w_fc,
                          const float* __restrict__ b_fc,
                          float* __restrict__ out) {
    int t = blockIdx.x;
    int j = threadIdx.x;
    float v = w_fc[j] * g_hs[t * HID + j];
#pragma unroll
    for (int off = 16; off > 0; off >>= 1)
        v += __shfl_xor_sync(0xFFFFFFFFu, v, off);
    if (j == 0) out[t] = v + b_fc[0];
}

// ---------------------------------------------------------------------------
extern "C" void kernel_launch(void* const* d_in, const int* in_sizes, int n_in,
                              void* d_out, int out_size) {
    const float* x    = (const float*)d_in[0];
    const float* w_ih = (const float*)d_in[1];
    const float* w_hh = (const float*)d_in[2];
    const float* b_ih = (const float*)d_in[3];
    const float* b_hh = (const float*)d_in[4];
    const float* w_fc = (const float*)d_in[5];
    const float* b_fc = (const float*)d_in[6];
    float* out = (float*)d_out;

    precompute_xg<<<(T_STEPS * G3 + 255) / 256, 256>>>(x, w_ih, b_ih, b_hh);
    gru_seq<<<1, 192>>>(w_hh, b_hh);
    fc_kernel<<<T_STEPS, HID>>>(w_fc, b_fc, out);
}